// round 2
// baseline (speedup 1.0000x reference)
#include <cuda_runtime.h>

#define B_DIM 16
#define G_DIM 1708
#define H_DIM 5
#define NC 28          // Taylor terms n = 0..27 (multiple of 4 for chain split)
#define NTHREADS 256
#define NWARPS 8

// Per-head scratch: [H][B][G]; combine is done by the last CTA per b (deterministic order).
__device__ float g_head[H_DIM * B_DIM * G_DIM];
__device__ int   g_cnt[B_DIM];   // zero-initialized; reset by combiner each launch

__constant__ float c_invfact[NC] = {
    1.0f, 1.0f, 0.5f,
    1.6666666666666666e-01f, 4.1666666666666664e-02f, 8.3333333333333332e-03f,
    1.3888888888888889e-03f, 1.9841269841269841e-04f, 2.4801587301587302e-05f,
    2.7557319223985893e-06f, 2.7557319223985894e-07f, 2.5052108385441720e-08f,
    2.0876756987868100e-09f, 1.6059043836821616e-10f, 1.1470745597729726e-11f,
    7.6471637318198174e-13f, 4.7794773323873859e-14f, 2.8114572543455210e-15f,
    1.5619206968586228e-16f, 8.2206352466243295e-18f, 4.1103176233121648e-19f,
    1.9572941063391263e-20f, 8.8967913924505741e-22f, 3.8681701706306840e-23f,
    1.6117375710961184e-24f, 6.4469502843844736e-26f, 2.4795962632247976e-27f,
    9.1836898637955460e-29f };

// One CTA per (batch b, head h).
// out_row[i] = (num(q_i) - exp(q_i*k_i)*v_i) / den(q_i)
// den(u) = sum_j exp(u*k_j) = sum_n (S_n/n!) u^n,  S_n = sum_j k_j^n
// num(u) = sum_j exp(u*k_j)*v_j = sum_n (M_n/n!) u^n,  M_n = sum_j k_j^n v_j
__global__ __launch_bounds__(NTHREADS, 1)
void attn_fused_kernel(const float* __restrict__ x,  const float* __restrict__ WQ,
                       const float* __restrict__ WK, const float* __restrict__ WV,
                       const float* __restrict__ W0, float* __restrict__ out) {
    const int b = blockIdx.x;
    const int h = blockIdx.y;

    __shared__ float sq[G_DIM], sk[G_DIM], sv[G_DIM];
    __shared__ float wS[NWARPS][NC], wM[NWARPS][NC];
    __shared__ float cS[NC], cM[NC];
    __shared__ float wkmax[NWARPS], wkmin[NWARPS];
    __shared__ float s_kmax, s_kmin;
    __shared__ int   s_last;

    const int tid = threadIdx.x;
    const float* __restrict__ xb = x  + b * G_DIM;
    const float* __restrict__ wq = WQ + h * G_DIM;
    const float* __restrict__ wk = WK + h * G_DIM;
    const float* __restrict__ wv = WV + h * G_DIM;

    // Stage q/k/v for this (b,h) into smem.
    for (int j = tid; j < G_DIM; j += NTHREADS) {
        float xv = xb[j];
        sq[j] = xv * wq[j];
        sk[j] = xv * wk[j];
        sv[j] = xv * wv[j];
    }
    __syncthreads();

    // ---- Moments: 4 independent power chains (step k^4) to break FMUL latency chain.
    float S[NC], M[NC];
#pragma unroll
    for (int n = 0; n < NC; n++) { S[n] = 0.f; M[n] = 0.f; }
    float kmax = -1e30f, kmin = 1e30f;

    for (int j = tid; j < G_DIM; j += NTHREADS) {
        const float k = sk[j];
        const float v = sv[j];
        kmax = fmaxf(kmax, k);
        kmin = fminf(kmin, k);
        const float k2 = k * k;
        const float k4 = k2 * k2;
        float p0 = 1.f, p1 = k, p2 = k2, p3 = k2 * k;
#pragma unroll
        for (int n = 0; n < NC; n += 4) {
            S[n + 0] += p0;  M[n + 0] = fmaf(p0, v, M[n + 0]);
            S[n + 1] += p1;  M[n + 1] = fmaf(p1, v, M[n + 1]);
            S[n + 2] += p2;  M[n + 2] = fmaf(p2, v, M[n + 2]);
            S[n + 3] += p3;  M[n + 3] = fmaf(p3, v, M[n + 3]);
            p0 *= k4; p1 *= k4; p2 *= k4; p3 *= k4;
        }
    }

    // Warp butterfly reduce.
#pragma unroll
    for (int n = 0; n < NC; n++) {
#pragma unroll
        for (int o = 16; o > 0; o >>= 1) {
            S[n] += __shfl_xor_sync(0xffffffffu, S[n], o);
            M[n] += __shfl_xor_sync(0xffffffffu, M[n], o);
        }
    }
    for (int o = 16; o > 0; o >>= 1) {
        kmax = fmaxf(kmax, __shfl_xor_sync(0xffffffffu, kmax, o));
        kmin = fminf(kmin, __shfl_xor_sync(0xffffffffu, kmin, o));
    }

    const int wid = tid >> 5, lane = tid & 31;
    if (lane == 0) {
#pragma unroll
        for (int n = 0; n < NC; n++) { wS[wid][n] = S[n]; wM[wid][n] = M[n]; }
        wkmax[wid] = kmax;
        wkmin[wid] = kmin;
    }
    __syncthreads();

    // Cross-warp finalize: coefficients c_n = (Σ partials) / n!
    if (tid < NC) {
        float s = 0.f;
        for (int w = 0; w < NWARPS; w++) s += wS[w][tid];
        cS[tid] = s * c_invfact[tid];
    } else if (tid < 2 * NC) {
        const int n = tid - NC;
        float s = 0.f;
        for (int w = 0; w < NWARPS; w++) s += wM[w][n];
        cM[n] = s * c_invfact[n];
    } else if (tid == 2 * NC) {
        float a = -1e30f, c = 1e30f;
        for (int w = 0; w < NWARPS; w++) {
            a = fmaxf(a, wkmax[w]);
            c = fminf(c, wkmin[w]);
        }
        s_kmax = a;
        s_kmin = c;
    }
    __syncthreads();

    const float kam = fmaxf(fabsf(s_kmax), fabsf(s_kmin));
    float* __restrict__ dst = g_head + (h * B_DIM + b) * G_DIM;

    // ---- Per-row evaluation: 2 rows per iteration (4 independent Horner chains).
    for (int i0 = tid; i0 < G_DIM; i0 += 2 * NTHREADS) {
        const int  i1   = i0 + NTHREADS;
        const bool has1 = (i1 < G_DIM);
        const float u0 = sq[i0];
        const float u1 = has1 ? sq[i1] : 0.f;

        if (fmaxf(fabsf(u0), fabsf(u1)) * kam <= 6.0f) {
            float den0 = cS[NC - 1], num0 = cM[NC - 1];
            float den1 = den0,       num1 = num0;
#pragma unroll
            for (int n = NC - 2; n >= 0; n--) {
                const float cs = cS[n], cm = cM[n];
                den0 = fmaf(den0, u0, cs);
                num0 = fmaf(num0, u0, cm);
                den1 = fmaf(den1, u1, cs);
                num1 = fmaf(num1, u1, cm);
            }
            const float e0 = __expf(u0 * sk[i0]);          // diagonal, masked post-softmax
            dst[i0] = (num0 - e0 * sv[i0]) / den0;
            if (has1) {
                const float e1 = __expf(u1 * sk[i1]);
                dst[i1] = (num1 - e1 * sv[i1]) / den1;
            }
        } else {
            // Exact fallback (max-subtracted); should not trigger on this data.
            for (int t = 0; t < 2; t++) {
                const int i = t ? i1 : i0;
                if (t && !has1) break;
                const float u = sq[i];
                const float m = (u > 0.f) ? u * s_kmax : u * s_kmin;
                float s1 = 0.f, s2 = 0.f;
                for (int j = 0; j < G_DIM; j++) {
                    const float e = __expf(fmaf(u, sk[j], -m));
                    s1 += e;
                    s2 = fmaf(e, sv[j], s2);
                }
                const float eii = __expf(fmaf(u, sk[i], -m));
                dst[i] = (s2 - eii * sv[i]) / s1;
            }
        }
    }

    // ---- Last CTA per b does the weighted head combine (single launch, no 2nd kernel).
    __threadfence();          // make this thread's g_head stores globally visible
    __syncthreads();          // all threads fenced
    if (tid == 0) {
        const int old = atomicAdd(&g_cnt[b], 1);
        s_last = (old == H_DIM - 1);
    }
    __syncthreads();

    if (s_last) {
        __threadfence();      // acquire: other CTAs' g_head writes now visible
        float w0c[H_DIM];
#pragma unroll
        for (int hh = 0; hh < H_DIM; hh++) w0c[hh] = W0[hh];

        const float* __restrict__ base = g_head + b * G_DIM;
        for (int i = tid; i < G_DIM; i += NTHREADS) {
            float acc = 0.f;
#pragma unroll
            for (int hh = 0; hh < H_DIM; hh++)
                acc = fmaf(w0c[hh], base[hh * B_DIM * G_DIM + i], acc);
            out[b * G_DIM + i] = acc;
        }
        __syncthreads();
        if (tid == 0) g_cnt[b] = 0;   // reset for next graph replay
    }
}

extern "C" void kernel_launch(void* const* d_in, const int* in_sizes, int n_in,
                              void* d_out, int out_size) {
    const float* x  = (const float*)d_in[0];
    const float* WQ = (const float*)d_in[1];
    const float* WK = (const float*)d_in[2];
    const float* WV = (const float*)d_in[3];
    const float* W0 = (const float*)d_in[4];
    float* out = (float*)d_out;

    dim3 grid(B_DIM, H_DIM);
    attn_fused_kernel<<<grid, NTHREADS>>>(x, WQ, WK, WV, W0, out);
}

// round 3
// speedup vs baseline: 1.2809x; 1.2809x over previous
#include <cuda_runtime.h>

#define B_DIM 16
#define G_DIM 1708
#define H_DIM 5
#define NC 24            // Taylor terms n = 0..23 (6^24/24! ~ 2e-8 rel at threshold)
#define NTHREADS 256
#define NWARPS 8
#define NCTAS (B_DIM * H_DIM)          // 80
#define CHUNK ((G_DIM + H_DIM - 1) / H_DIM)  // 342 rows per slice

// Coefficient table: per (b,h): [S0..S23, M0..M23] (already /n!). Plus kmin/kmax.
__device__ float g_coef[NCTAS * 2 * NC];
__device__ float g_kmm[NCTAS * 2];     // [kmax, kmin]
__device__ unsigned int g_bar;          // monotone grid barrier (replay-safe)

__constant__ float c_invfact[NC] = {
    1.0f, 1.0f, 0.5f,
    1.6666666666666666e-01f, 4.1666666666666664e-02f, 8.3333333333333332e-03f,
    1.3888888888888889e-03f, 1.9841269841269841e-04f, 2.4801587301587302e-05f,
    2.7557319223985893e-06f, 2.7557319223985894e-07f, 2.5052108385441720e-08f,
    2.0876756987868100e-09f, 1.6059043836821616e-10f, 1.1470745597729726e-11f,
    7.6471637318198174e-13f, 4.7794773323873859e-14f, 2.8114572543455210e-15f,
    1.5619206968586228e-16f, 8.2206352466243295e-18f, 4.1103176233121648e-19f,
    1.9572941063391263e-20f, 8.8967913924505741e-22f, 3.8681701706306840e-23f };

// den(u) = sum_j exp(u*k_j) = sum_n (S_n/n!) u^n,   S_n = sum_j k_j^n
// num(u) = sum_j exp(u*k_j)*v_j = sum_n (M_n/n!) u^n, M_n = sum_j k_j^n v_j
// out[b,i] = sum_h W0[h] * (num_h(q_i) - exp(q_i*k_i)*v_i) / den_h(q_i)
__global__ __launch_bounds__(NTHREADS, 1)
void attn_twophase_kernel(const float* __restrict__ x,  const float* __restrict__ WQ,
                          const float* __restrict__ WK, const float* __restrict__ WV,
                          const float* __restrict__ W0, float* __restrict__ out) {
    const int blk = blockIdx.x;          // 0..79
    const int tid = threadIdx.x;
    const int wid = tid >> 5, lane = tid & 31;

    __shared__ float wS[NWARPS][NC], wM[NWARPS][NC];
    __shared__ float wkmax[NWARPS], wkmin[NWARPS];
    __shared__ float scoef[H_DIM][2 * NC];
    __shared__ float skmm[H_DIM][2];

    // ================= PHASE 1: moments for (b1, h1) =================
    {
        const int b1 = blk / H_DIM;
        const int h1 = blk % H_DIM;
        const float* __restrict__ xb = x  + b1 * G_DIM;
        const float* __restrict__ wk = WK + h1 * G_DIM;
        const float* __restrict__ wv = WV + h1 * G_DIM;

        float S[NC], M[NC];
#pragma unroll
        for (int n = 0; n < NC; n++) { S[n] = 0.f; M[n] = 0.f; }
        float kmax = -1e30f, kmin = 1e30f;

#pragma unroll 2
        for (int j = tid; j < G_DIM; j += NTHREADS) {
            const float xv = xb[j];
            const float k  = xv * wk[j];
            const float v  = xv * wv[j];
            kmax = fmaxf(kmax, k);
            kmin = fminf(kmin, k);
            const float k2 = k * k;
            const float k4 = k2 * k2;
            float p0 = 1.f, p1 = k, p2 = k2, p3 = k2 * k;
#pragma unroll
            for (int n = 0; n < NC; n += 4) {
                S[n + 0] += p0;  M[n + 0] = fmaf(p0, v, M[n + 0]);
                S[n + 1] += p1;  M[n + 1] = fmaf(p1, v, M[n + 1]);
                S[n + 2] += p2;  M[n + 2] = fmaf(p2, v, M[n + 2]);
                S[n + 3] += p3;  M[n + 3] = fmaf(p3, v, M[n + 3]);
                p0 *= k4; p1 *= k4; p2 *= k4; p3 *= k4;
            }
        }

        // Warp butterfly reduce.
#pragma unroll
        for (int n = 0; n < NC; n++) {
#pragma unroll
            for (int o = 16; o > 0; o >>= 1) {
                S[n] += __shfl_xor_sync(0xffffffffu, S[n], o);
                M[n] += __shfl_xor_sync(0xffffffffu, M[n], o);
            }
        }
        for (int o = 16; o > 0; o >>= 1) {
            kmax = fmaxf(kmax, __shfl_xor_sync(0xffffffffu, kmax, o));
            kmin = fminf(kmin, __shfl_xor_sync(0xffffffffu, kmin, o));
        }
        if (lane == 0) {
#pragma unroll
            for (int n = 0; n < NC; n++) { wS[wid][n] = S[n]; wM[wid][n] = M[n]; }
            wkmax[wid] = kmax;
            wkmin[wid] = kmin;
        }
        __syncthreads();

        // Cross-warp finalize -> write 48 coefficients straight to global.
        if (tid < NC) {
            float s = 0.f;
            for (int w = 0; w < NWARPS; w++) s += wS[w][tid];
            g_coef[blk * 2 * NC + tid] = s * c_invfact[tid];
        } else if (tid < 2 * NC) {
            const int n = tid - NC;
            float s = 0.f;
            for (int w = 0; w < NWARPS; w++) s += wM[w][n];
            g_coef[blk * 2 * NC + tid] = s * c_invfact[n];
        } else if (tid == 2 * NC) {
            float a = -1e30f, c = 1e30f;
            for (int w = 0; w < NWARPS; w++) {
                a = fmaxf(a, wkmax[w]);
                c = fminf(c, wkmin[w]);
            }
            g_kmm[blk * 2 + 0] = a;
            g_kmm[blk * 2 + 1] = c;
        }
    }

    // ================= GRID BARRIER (all 80 CTAs co-resident) =================
    __threadfence();                 // publish the ~50 floats this CTA wrote
    __syncthreads();
    if (tid == 0) {
        const unsigned old = atomicAdd(&g_bar, 1u);
        const unsigned target = (old / NCTAS) * NCTAS + NCTAS;  // monotone: replay-safe
        volatile unsigned* vb = &g_bar;
        while ((int)(*vb - target) < 0) { __nanosleep(64); }
    }
    __syncthreads();
    __threadfence();                 // acquire side before reading others' coefs

    // ================= PHASE 2: eval rows [r0,r1) of batch b2, all heads =======
    const int b2 = blk / H_DIM;
    const int slice = blk % H_DIM;
    const int r0 = slice * CHUNK;
    const int r1 = min(G_DIM, r0 + CHUNK);

    // Stage the 5 heads' coefficients for this batch into smem.
    if (tid < H_DIM * 2 * NC) {
        const int h = tid / (2 * NC);
        const int n = tid % (2 * NC);
        scoef[h][n] = g_coef[(b2 * H_DIM + h) * 2 * NC + n];
    } else if (tid < H_DIM * 2 * NC + 2 * H_DIM) {
        const int t = tid - H_DIM * 2 * NC;
        skmm[t / 2][t % 2] = g_kmm[(b2 * H_DIM + t / 2) * 2 + (t % 2)];
    }
    __syncthreads();

    float w0r[H_DIM];
#pragma unroll
    for (int h = 0; h < H_DIM; h++) w0r[h] = W0[h];

    const float* __restrict__ xb2 = x + b2 * G_DIM;

    for (int i = r0 + tid; i < r1; i += NTHREADS) {
        const float xv = xb2[i];
        float acc = 0.f;
#pragma unroll
        for (int h = 0; h < H_DIM; h++) {
            const float u  = xv * WQ[h * G_DIM + i];
            const float ki = xv * WK[h * G_DIM + i];
            const float vi = xv * WV[h * G_DIM + i];
            const float km = skmm[h][0], kn = skmm[h][1];
            const float kam = fmaxf(fabsf(km), fabsf(kn));
            float o;
            if (fabsf(u) * kam <= 6.0f) {
                float den = scoef[h][NC - 1];
                float num = scoef[h][2 * NC - 1];
#pragma unroll
                for (int n = NC - 2; n >= 0; n--) {
                    den = fmaf(den, u, scoef[h][n]);
                    num = fmaf(num, u, scoef[h][NC + n]);
                }
                const float eii = __expf(u * ki);      // diagonal, masked post-softmax
                o = (num - eii * vi) * __frcp_rn(den);
            } else {
                // Exact fallback (max-subtracted); should not trigger on this data.
                const float m = (u > 0.f) ? u * km : u * kn;
                float s1 = 0.f, s2 = 0.f;
                const float* __restrict__ wkh = WK + h * G_DIM;
                const float* __restrict__ wvh = WV + h * G_DIM;
                for (int j = 0; j < G_DIM; j++) {
                    const float xj = xb2[j];
                    const float kj = xj * wkh[j];
                    const float vj = xj * wvh[j];
                    const float e  = __expf(fmaf(u, kj, -m));
                    s1 += e;
                    s2 = fmaf(e, vj, s2);
                }
                const float eii = __expf(fmaf(u, ki, -m));
                o = (s2 - eii * vi) / s1;
            }
            acc = fmaf(w0r[h], o, acc);
        }
        out[b2 * G_DIM + i] = acc;
    }
}

extern "C" void kernel_launch(void* const* d_in, const int* in_sizes, int n_in,
                              void* d_out, int out_size) {
    const float* x  = (const float*)d_in[0];
    const float* WQ = (const float*)d_in[1];
    const float* WK = (const float*)d_in[2];
    const float* WV = (const float*)d_in[3];
    const float* W0 = (const float*)d_in[4];
    float* out = (float*)d_out;

    attn_twophase_kernel<<<NCTAS, NTHREADS>>>(x, WQ, WK, WV, W0, out);
}

// round 4
// speedup vs baseline: 1.7551x; 1.3703x over previous
#include <cuda_runtime.h>

#define B_DIM 16
#define G_DIM 1708
#define GV4   (G_DIM / 4)        // 427, exact
#define H_DIM 5
#define NC 24                    // Taylor n = 0..23; 6^24/24! ~ 2e-8 at guard
#define NTHREADS 256
#define NWARPS 8

__constant__ float c_invfact[NC] = {
    1.0f, 1.0f, 0.5f,
    1.6666666666666666e-01f, 4.1666666666666664e-02f, 8.3333333333333332e-03f,
    1.3888888888888889e-03f, 1.9841269841269841e-04f, 2.4801587301587302e-05f,
    2.7557319223985893e-06f, 2.7557319223985894e-07f, 2.5052108385441720e-08f,
    2.0876756987868100e-09f, 1.6059043836821616e-10f, 1.1470745597729726e-11f,
    7.6471637318198174e-13f, 4.7794773323873859e-14f, 2.8114572543455210e-15f,
    1.5619206968586228e-16f, 8.2206352466243295e-18f, 4.1103176233121648e-19f,
    1.9572941063391263e-20f, 8.8967913924505741e-22f, 3.8681701706306840e-23f };

// Exact (max-subtracted) row evaluation; never taken on this data.
// __noinline__ keeps the hot loop body small (I$ throttle hits low-grid kernels).
__device__ __noinline__ float exact_row(float u, const float* __restrict__ xb,
                                        const float* __restrict__ wkh,
                                        const float* __restrict__ wvh,
                                        float km, float kn, float ki, float vi) {
    const float m = (u > 0.f) ? u * km : u * kn;
    float s1 = 0.f, s2 = 0.f;
    for (int j = 0; j < G_DIM; j++) {
        const float xj = xb[j];
        const float kj = xj * wkh[j];
        const float vj = xj * wvh[j];
        const float e  = __expf(fmaf(u, kj, -m));
        s1 += e;
        s2 = fmaf(e, vj, s2);
    }
    const float eii = __expf(fmaf(u, ki, -m));
    return (s2 - eii * vi) / s1;
}

// One CTA per (b,h). Moments -> coefficients -> row eval -> red.add into out.
// den(u) = sum_n (S_n/n!) u^n,  num(u) = sum_n (M_n/n!) u^n
// out[b,i] += W0[h] * (num(q_i) - exp(q_i*k_i)*v_i) / den(q_i)
__global__ __launch_bounds__(NTHREADS, 1)
void attn_head_red_kernel(const float* __restrict__ x,  const float* __restrict__ WQ,
                          const float* __restrict__ WK, const float* __restrict__ WV,
                          const float* __restrict__ W0, float* __restrict__ out) {
    const int b = blockIdx.x;
    const int h = blockIdx.y;
    const int tid = threadIdx.x;
    const int wid = tid >> 5, lane = tid & 31;

    __shared__ float wS[NWARPS][NC], wM[NWARPS][NC];
    __shared__ float cS[NC], cM[NC];
    __shared__ float wkmax[NWARPS], wkmin[NWARPS];
    __shared__ float s_kmax, s_kmin;

    const float* __restrict__ xb = x  + b * G_DIM;
    const float* __restrict__ wq = WQ + h * G_DIM;
    const float* __restrict__ wk = WK + h * G_DIM;
    const float* __restrict__ wv = WV + h * G_DIM;
    const float4* __restrict__ xb4 = (const float4*)xb;   // 1708*4B offsets are 16B-aligned
    const float4* __restrict__ wq4 = (const float4*)wq;
    const float4* __restrict__ wk4 = (const float4*)wk;
    const float4* __restrict__ wv4 = (const float4*)wv;

    // ---- Moments (vectorized float4, 4-way power chains per element).
    float S[NC], M[NC];
#pragma unroll
    for (int n = 0; n < NC; n++) { S[n] = 0.f; M[n] = 0.f; }
    float kmax = -1e30f, kmin = 1e30f;

    for (int j = tid; j < GV4; j += NTHREADS) {
        const float4 xv = xb4[j];
        const float4 kw = wk4[j];
        const float4 vw = wv4[j];
        const float k0 = xv.x * kw.x, v0 = xv.x * vw.x;
        const float k1 = xv.y * kw.y, v1 = xv.y * vw.y;
        const float k2 = xv.z * kw.z, v2 = xv.z * vw.z;
        const float k3 = xv.w * kw.w, v3 = xv.w * vw.w;
        kmax = fmaxf(fmaxf(fmaxf(kmax, k0), fmaxf(k1, k2)), k3);
        kmin = fminf(fminf(fminf(kmin, k0), fminf(k1, k2)), k3);

#pragma unroll
        for (int e = 0; e < 4; e++) {
            const float k = (e == 0) ? k0 : (e == 1) ? k1 : (e == 2) ? k2 : k3;
            const float v = (e == 0) ? v0 : (e == 1) ? v1 : (e == 2) ? v2 : v3;
            const float ksq = k * k;
            const float kq  = ksq * ksq;
            float p0 = 1.f, p1 = k, p2 = ksq, p3 = ksq * k;
#pragma unroll
            for (int n = 0; n < NC; n += 4) {
                S[n + 0] += p0;  M[n + 0] = fmaf(p0, v, M[n + 0]);
                S[n + 1] += p1;  M[n + 1] = fmaf(p1, v, M[n + 1]);
                S[n + 2] += p2;  M[n + 2] = fmaf(p2, v, M[n + 2]);
                S[n + 3] += p3;  M[n + 3] = fmaf(p3, v, M[n + 3]);
                p0 *= kq; p1 *= kq; p2 *= kq; p3 *= kq;
            }
        }
    }

    // ---- Warp butterfly reduce.
#pragma unroll
    for (int n = 0; n < NC; n++) {
#pragma unroll
        for (int o = 16; o > 0; o >>= 1) {
            S[n] += __shfl_xor_sync(0xffffffffu, S[n], o);
            M[n] += __shfl_xor_sync(0xffffffffu, M[n], o);
        }
    }
    for (int o = 16; o > 0; o >>= 1) {
        kmax = fmaxf(kmax, __shfl_xor_sync(0xffffffffu, kmax, o));
        kmin = fminf(kmin, __shfl_xor_sync(0xffffffffu, kmin, o));
    }
    if (lane == 0) {
#pragma unroll
        for (int n = 0; n < NC; n++) { wS[wid][n] = S[n]; wM[wid][n] = M[n]; }
        wkmax[wid] = kmax;
        wkmin[wid] = kmin;
    }
    __syncthreads();

    // ---- Cross-warp finalize: c_n = (Σ partials) / n!
    if (tid < NC) {
        float s = 0.f;
        for (int w = 0; w < NWARPS; w++) s += wS[w][tid];
        cS[tid] = s * c_invfact[tid];
    } else if (tid < 2 * NC) {
        const int n = tid - NC;
        float s = 0.f;
        for (int w = 0; w < NWARPS; w++) s += wM[w][n];
        cM[n] = s * c_invfact[n];
    } else if (tid == 2 * NC) {
        float a = -1e30f, c = 1e30f;
        for (int w = 0; w < NWARPS; w++) {
            a = fmaxf(a, wkmax[w]);
            c = fminf(c, wkmin[w]);
        }
        s_kmax = a;
        s_kmin = c;
    }
    __syncthreads();

    const float kam = fmaxf(fabsf(s_kmax), fabsf(s_kmin));
    const float w0h = W0[h];
    float* __restrict__ ob = out + b * G_DIM;

    // ---- Row eval (4 rows / thread-iter, 8 independent Horner chains), red.add out.
    for (int j = tid; j < GV4; j += NTHREADS) {
        const float4 xv = xb4[j];
        const float4 qw = wq4[j];
        const float4 kw = wk4[j];
        const float4 vw = wv4[j];
        const float u0 = xv.x * qw.x, u1 = xv.y * qw.y, u2 = xv.z * qw.z, u3 = xv.w * qw.w;
        const float umax = fmaxf(fmaxf(fabsf(u0), fabsf(u1)), fmaxf(fabsf(u2), fabsf(u3)));

        float o0, o1, o2, o3;
        if (umax * kam <= 6.0f) {
            float d0 = cS[NC - 1], d1 = d0, d2 = d0, d3 = d0;
            float m0 = cM[NC - 1], m1 = m0, m2 = m0, m3 = m0;
#pragma unroll
            for (int n = NC - 2; n >= 0; n--) {
                const float cs = cS[n], cm = cM[n];
                d0 = fmaf(d0, u0, cs);  m0 = fmaf(m0, u0, cm);
                d1 = fmaf(d1, u1, cs);  m1 = fmaf(m1, u1, cm);
                d2 = fmaf(d2, u2, cs);  m2 = fmaf(m2, u2, cm);
                d3 = fmaf(d3, u3, cs);  m3 = fmaf(m3, u3, cm);
            }
            // diagonal masked post-softmax: subtract exp(u*k_i)*v_i from numerator
            const float e0 = __expf(u0 * (xv.x * kw.x));
            const float e1 = __expf(u1 * (xv.y * kw.y));
            const float e2 = __expf(u2 * (xv.z * kw.z));
            const float e3 = __expf(u3 * (xv.w * kw.w));
            o0 = (m0 - e0 * (xv.x * vw.x)) * __frcp_rn(d0);
            o1 = (m1 - e1 * (xv.y * vw.y)) * __frcp_rn(d1);
            o2 = (m2 - e2 * (xv.z * vw.z)) * __frcp_rn(d2);
            o3 = (m3 - e3 * (xv.w * vw.w)) * __frcp_rn(d3);
        } else {
            o0 = exact_row(u0, xb, wk, wv, s_kmax, s_kmin, xv.x * kw.x, xv.x * vw.x);
            o1 = exact_row(u1, xb, wk, wv, s_kmax, s_kmin, xv.y * kw.y, xv.y * vw.y);
            o2 = exact_row(u2, xb, wk, wv, s_kmax, s_kmin, xv.z * kw.z, xv.z * vw.z);
            o3 = exact_row(u3, xb, wk, wv, s_kmax, s_kmin, xv.w * kw.w, xv.w * vw.w);
        }
        const int i = 4 * j;
        atomicAdd(ob + i + 0, w0h * o0);
        atomicAdd(ob + i + 1, w0h * o1);
        atomicAdd(ob + i + 2, w0h * o2);
        atomicAdd(ob + i + 3, w0h * o3);
    }
}

extern "C" void kernel_launch(void* const* d_in, const int* in_sizes, int n_in,
                              void* d_out, int out_size) {
    const float* x  = (const float*)d_in[0];
    const float* WQ = (const float*)d_in[1];
    const float* WK = (const float*)d_in[2];
    const float* WV = (const float*)d_in[3];
    const float* W0 = (const float*)d_in[4];
    float* out = (float*)d_out;

    // Zero the accumulator (graph-capturable memset node; no allocation).
    cudaMemsetAsync(out, 0, (size_t)out_size * sizeof(float), 0);

    dim3 grid(B_DIM, H_DIM);
    attn_head_red_kernel<<<grid, NTHREADS>>>(x, WQ, WK, WV, W0, out);
}

// round 6
// speedup vs baseline: 1.8024x; 1.0269x over previous
#include <cuda_runtime.h>

#define B_DIM 16
#define G_DIM 1708
#define GV4   (G_DIM / 4)        // 427, exact
#define H_DIM 5
#define NC 16                    // Taylor n = 0..15; 4.5^16/16!/e^4.5 ~ 1.5e-5 at guard
#define GUARD 4.5f
#define NTHREADS 512
#define NWARPS 16

__constant__ float c_invfact[NC] = {
    1.0f, 1.0f, 0.5f,
    1.6666666666666666e-01f, 4.1666666666666664e-02f, 8.3333333333333332e-03f,
    1.3888888888888889e-03f, 1.9841269841269841e-04f, 2.4801587301587302e-05f,
    2.7557319223985893e-06f, 2.7557319223985894e-07f, 2.5052108385441720e-08f,
    2.0876756987868100e-09f, 1.6059043836821616e-10f, 1.1470745597729726e-11f,
    7.6471637318198174e-13f };

// Exact (max-subtracted) row evaluation; never taken on this data.
// __noinline__ keeps the hot loop body small (I$ throttle hits low-grid kernels).
__device__ __noinline__ float exact_row(float u, const float* __restrict__ xb,
                                        const float* __restrict__ wkh,
                                        const float* __restrict__ wvh,
                                        float km, float kn, float ki, float vi) {
    const float m = (u > 0.f) ? u * km : u * kn;
    float s1 = 0.f, s2 = 0.f;
    for (int j = 0; j < G_DIM; j++) {
        const float xj = xb[j];
        const float kj = xj * wkh[j];
        const float vj = xj * wvh[j];
        const float e  = __expf(fmaf(u, kj, -m));
        s1 += e;
        s2 = fmaf(e, vj, s2);
    }
    const float eii = __expf(fmaf(u, ki, -m));
    return (s2 - eii * vi) / s1;
}

// One CTA per (b,h). Moments -> coefficients -> row eval -> red.add into out.
// den(u) = sum_n (S_n/n!) u^n,  num(u) = sum_n (M_n/n!) u^n
// out[b,i] += W0[h] * (num(q_i) - exp(q_i*k_i)*v_i) / den(q_i)
__global__ __launch_bounds__(NTHREADS, 1)
void attn_head_red_kernel(const float* __restrict__ x,  const float* __restrict__ WQ,
                          const float* __restrict__ WK, const float* __restrict__ WV,
                          const float* __restrict__ W0, float* __restrict__ out) {
    const int b = blockIdx.x;
    const int h = blockIdx.y;
    const int tid = threadIdx.x;
    const int wid = tid >> 5, lane = tid & 31;

    __shared__ float wR[NWARPS][32];        // per-warp reduced values (S0..15, M0..15)
    __shared__ float cS[NC], cM[NC];
    __shared__ float wkmax[NWARPS], wkmin[NWARPS];
    __shared__ float s_kmax, s_kmin;

    const float* __restrict__ xb = x  + b * G_DIM;
    const float* __restrict__ wq = WQ + h * G_DIM;
    const float* __restrict__ wk = WK + h * G_DIM;
    const float* __restrict__ wv = WV + h * G_DIM;
    const float4* __restrict__ xb4 = (const float4*)xb;   // offsets 16B-aligned
    const float4* __restrict__ wq4 = (const float4*)wq;
    const float4* __restrict__ wk4 = (const float4*)wk;
    const float4* __restrict__ wv4 = (const float4*)wv;

    // ---- Moments (float4-vectorized; 1 strided iteration/thread at 512 threads).
    // R[0..15] = S moments, R[16..31] = M moments.
    float R[32];
#pragma unroll
    for (int n = 0; n < 32; n++) R[n] = 0.f;
    float kmax = -1e30f, kmin = 1e30f;

    for (int j = tid; j < GV4; j += NTHREADS) {
        const float4 xv = xb4[j];
        const float4 kw = wk4[j];
        const float4 vw = wv4[j];
        const float k0 = xv.x * kw.x, v0 = xv.x * vw.x;
        const float k1 = xv.y * kw.y, v1 = xv.y * vw.y;
        const float k2 = xv.z * kw.z, v2 = xv.z * vw.z;
        const float k3 = xv.w * kw.w, v3 = xv.w * vw.w;
        kmax = fmaxf(fmaxf(fmaxf(kmax, k0), fmaxf(k1, k2)), k3);
        kmin = fminf(fminf(fminf(kmin, k0), fminf(k1, k2)), k3);

#pragma unroll
        for (int e = 0; e < 4; e++) {
            const float k = (e == 0) ? k0 : (e == 1) ? k1 : (e == 2) ? k2 : k3;
            const float v = (e == 0) ? v0 : (e == 1) ? v1 : (e == 2) ? v2 : v3;
            const float ksq = k * k;
            const float kq  = ksq * ksq;
            float p0 = 1.f, p1 = k, p2 = ksq, p3 = ksq * k;
#pragma unroll
            for (int n = 0; n < NC; n += 4) {
                R[n + 0]      += p0;  R[NC + n + 0] = fmaf(p0, v, R[NC + n + 0]);
                R[n + 1]      += p1;  R[NC + n + 1] = fmaf(p1, v, R[NC + n + 1]);
                R[n + 2]      += p2;  R[NC + n + 2] = fmaf(p2, v, R[NC + n + 2]);
                R[n + 3]      += p3;  R[NC + n + 3] = fmaf(p3, v, R[NC + n + 3]);
                p0 *= kq; p1 *= kq; p2 *= kq; p3 *= kq;
            }
        }
    }

    // ---- Transpose-exchange warp reduce: 32 values across 32 lanes in 5 rounds.
    // After the loop, lane l holds the warp-sum of value index l in R[l].
#pragma unroll
    for (int s = 16; s > 0; s >>= 1) {
        const bool up = (lane & s) != 0;
#pragma unroll
        for (int i0 = 0; i0 < 32; i0++) {
            if ((i0 & s) == 0) {
                const int i1 = i0 | s;
                const float send = up ? R[i0] : R[i1];
                const float recv = __shfl_xor_sync(0xffffffffu, send, s);
                if (up) R[i1] += recv; else R[i0] += recv;
            }
        }
    }
    float mine = R[0];
#pragma unroll
    for (int i = 1; i < 32; i++) mine = (lane == i) ? R[i] : mine;
    wR[wid][lane] = mine;

    // kmax/kmin: classic butterfly (only 2 values).
#pragma unroll
    for (int o = 16; o > 0; o >>= 1) {
        kmax = fmaxf(kmax, __shfl_xor_sync(0xffffffffu, kmax, o));
        kmin = fminf(kmin, __shfl_xor_sync(0xffffffffu, kmin, o));
    }
    if (lane == 0) { wkmax[wid] = kmax; wkmin[wid] = kmin; }
    __syncthreads();

    // ---- Cross-warp finalize: c_n = (Σ_w wR[w][n]) / n!
    if (tid < 32) {
        float s = 0.f;
#pragma unroll
        for (int w = 0; w < NWARPS; w++) s += wR[w][tid];
        if (tid < NC) cS[tid] = s * c_invfact[tid];
        else          cM[tid - NC] = s * c_invfact[tid - NC];
    } else if (tid == 32) {
        float a = -1e30f, c = 1e30f;
#pragma unroll
        for (int w = 0; w < NWARPS; w++) {
            a = fmaxf(a, wkmax[w]);
            c = fminf(c, wkmin[w]);
        }
        s_kmax = a;
        s_kmin = c;
    }
    __syncthreads();

    const float kam = fmaxf(fabsf(s_kmax), fabsf(s_kmin));
    const float w0h = W0[h];
    float* __restrict__ ob = out + b * G_DIM;

    // ---- Row eval (4 rows/iter, 8 independent Horner chains), red.add into out.
    for (int j = tid; j < GV4; j += NTHREADS) {
        const float4 xv = xb4[j];
        const float4 qw = wq4[j];
        const float4 kw = wk4[j];
        const float4 vw = wv4[j];
        const float u0 = xv.x * qw.x, u1 = xv.y * qw.y, u2 = xv.z * qw.z, u3 = xv.w * qw.w;
        const float umax = fmaxf(fmaxf(fabsf(u0), fabsf(u1)), fmaxf(fabsf(u2), fabsf(u3)));

        float o0, o1, o2, o3;
        if (umax * kam <= GUARD) {
            float d0 = cS[NC - 1], d1 = d0, d2 = d0, d3 = d0;
            float m0 = cM[NC - 1], m1 = m0, m2 = m0, m3 = m0;
#pragma unroll
            for (int n = NC - 2; n >= 0; n--) {
                const float cs = cS[n], cm = cM[n];
                d0 = fmaf(d0, u0, cs);  m0 = fmaf(m0, u0, cm);
                d1 = fmaf(d1, u1, cs);  m1 = fmaf(m1, u1, cm);
                d2 = fmaf(d2, u2, cs);  m2 = fmaf(m2, u2, cm);
                d3 = fmaf(d3, u3, cs);  m3 = fmaf(m3, u3, cm);
            }
            // diagonal masked post-softmax: subtract exp(u*k_i)*v_i from numerator
            const float e0 = __expf(u0 * (xv.x * kw.x));
            const float e1 = __expf(u1 * (xv.y * kw.y));
            const float e2 = __expf(u2 * (xv.z * kw.z));
            const float e3 = __expf(u3 * (xv.w * kw.w));
            o0 = (m0 - e0 * (xv.x * vw.x)) * __frcp_rn(d0);
            o1 = (m1 - e1 * (xv.y * vw.y)) * __frcp_rn(d1);
            o2 = (m2 - e2 * (xv.z * vw.z)) * __frcp_rn(d2);
            o3 = (m3 - e3 * (xv.w * vw.w)) * __frcp_rn(d3);
        } else {
            o0 = exact_row(u0, xb, wk, wv, s_kmax, s_kmin, xv.x * kw.x, xv.x * vw.x);
            o1 = exact_row(u1, xb, wk, wv, s_kmax, s_kmin, xv.y * kw.y, xv.y * vw.y);
            o2 = exact_row(u2, xb, wk, wv, s_kmax, s_kmin, xv.z * kw.z, xv.z * vw.z);
            o3 = exact_row(u3, xb, wk, wv, s_kmax, s_kmin, xv.w * kw.w, xv.w * vw.w);
        }
        const int i = 4 * j;
        atomicAdd(ob + i + 0, w0h * o0);
        atomicAdd(ob + i + 1, w0h * o1);
        atomicAdd(ob + i + 2, w0h * o2);
        atomicAdd(ob + i + 3, w0h * o3);
    }
}

extern "C" void kernel_launch(void* const* d_in, const int* in_sizes, int n_in,
                              void* d_out, int out_size) {
    const float* x  = (const float*)d_in[0];
    const float* WQ = (const float*)d_in[1];
    const float* WK = (const float*)d_in[2];
    const float* WV = (const float*)d_in[3];
    const float* W0 = (const float*)d_in[4];
    float* out = (float*)d_out;

    // Zero the accumulator (graph-capturable memset node; no allocation).
    cudaMemsetAsync(out, 0, (size_t)out_size * sizeof(float), 0);

    dim3 grid(B_DIM, H_DIM);
    attn_head_red_kernel<<<grid, NTHREADS>>>(x, WQ, WK, WV, W0, out);
}

// round 7
// speedup vs baseline: 2.2214x; 1.2325x over previous
#include <cuda_runtime.h>

#define B_DIM 16
#define G_DIM 1708
#define GV4   (G_DIM / 4)        // 427 < NTHREADS: exactly one float4 group per thread
#define H_DIM 5
#define NC 16                    // Taylor n = 0..15; 4.5^16/16!/e^4.5 ~ 1.5e-5 at guard
#define GUARD 4.5f
#define NTHREADS 512
#define NWARPS 16

__constant__ float c_invfact[NC] = {
    1.0f, 1.0f, 0.5f,
    1.6666666666666666e-01f, 4.1666666666666664e-02f, 8.3333333333333332e-03f,
    1.3888888888888889e-03f, 1.9841269841269841e-04f, 2.4801587301587302e-05f,
    2.7557319223985893e-06f, 2.7557319223985894e-07f, 2.5052108385441720e-08f,
    2.0876756987868100e-09f, 1.6059043836821616e-10f, 1.1470745597729726e-11f,
    7.6471637318198174e-13f };

// Exact fallback; never taken on this data. Shift m = |u|*kam >= max_j(u*k_j)
// is overflow-safe and cancels in the num/den ratio.
__device__ __noinline__ float exact_row(float u, const float* __restrict__ xb,
                                        const float* __restrict__ wkh,
                                        const float* __restrict__ wvh,
                                        float kam, float ki, float vi) {
    const float m = fabsf(u) * kam;
    float s1 = 0.f, s2 = 0.f;
    for (int j = 0; j < G_DIM; j++) {
        const float xj = xb[j];
        const float kj = xj * wkh[j];
        const float vj = xj * wvh[j];
        const float e  = __expf(fmaf(u, kj, -m));
        s1 += e;
        s2 = fmaf(e, vj, s2);
    }
    const float eii = __expf(fmaf(u, ki, -m));
    return (s2 - eii * vi) / s1;
}

// One CTA per (b,h). All per-thread data (one float4 group) loaded ONCE and
// retained in registers across moment accumulation, reduction, and row eval.
// den(u) = sum_n (S_n/n!) u^n,  num(u) = sum_n (M_n/n!) u^n
// out[b,i] += W0[h] * (num(q_i) - exp(q_i*k_i)*v_i) / den(q_i)
__global__ __launch_bounds__(NTHREADS, 1)
void attn_head_red_kernel(const float* __restrict__ x,  const float* __restrict__ WQ,
                          const float* __restrict__ WK, const float* __restrict__ WV,
                          const float* __restrict__ W0, float* __restrict__ out) {
    const int b = blockIdx.x;
    const int h = blockIdx.y;
    const int tid = threadIdx.x;
    const int wid = tid >> 5, lane = tid & 31;
    const bool act = (tid < GV4);

    __shared__ float wR[NWARPS][32];        // per-warp reduced (S0..15, M0..15)
    __shared__ float cS[NC], cM[NC];
    __shared__ float wkam[NWARPS];
    __shared__ float s_kam;

    const float4* __restrict__ xb4 = (const float4*)(x  + b * G_DIM);
    const float4* __restrict__ wq4 = (const float4*)(WQ + h * G_DIM);
    const float4* __restrict__ wk4 = (const float4*)(WK + h * G_DIM);
    const float4* __restrict__ wv4 = (const float4*)(WV + h * G_DIM);

    // ---- Load everything this thread will ever need (one DRAM round-trip).
    float4 xv = make_float4(0.f, 0.f, 0.f, 0.f), qw = xv, kw = xv, vw = xv;
    if (act) {
        xv = xb4[tid];
        qw = wq4[tid];   // prefetched here: latency hides under moments+reduction
        kw = wk4[tid];
        vw = wv4[tid];
    }
    const float k0 = xv.x * kw.x, v0 = xv.x * vw.x;
    const float k1 = xv.y * kw.y, v1 = xv.y * vw.y;
    const float k2 = xv.z * kw.z, v2 = xv.z * vw.z;
    const float k3 = xv.w * kw.w, v3 = xv.w * vw.w;

    float kam = fmaxf(fmaxf(fabsf(k0), fabsf(k1)), fmaxf(fabsf(k2), fabsf(k3)));

    // ---- Moments: R[0..15] = S_n partials, R[16..31] = M_n partials.
    float R[32];
#pragma unroll
    for (int n = 0; n < 32; n++) R[n] = 0.f;
    if (act) {
#pragma unroll
        for (int e = 0; e < 4; e++) {
            const float k = (e == 0) ? k0 : (e == 1) ? k1 : (e == 2) ? k2 : k3;
            const float v = (e == 0) ? v0 : (e == 1) ? v1 : (e == 2) ? v2 : v3;
            const float ksq = k * k;
            const float kq  = ksq * ksq;
            float p0 = 1.f, p1 = k, p2 = ksq, p3 = ksq * k;
#pragma unroll
            for (int n = 0; n < NC; n += 4) {
                R[n + 0]      += p0;  R[NC + n + 0] = fmaf(p0, v, R[NC + n + 0]);
                R[n + 1]      += p1;  R[NC + n + 1] = fmaf(p1, v, R[NC + n + 1]);
                R[n + 2]      += p2;  R[NC + n + 2] = fmaf(p2, v, R[NC + n + 2]);
                R[n + 3]      += p3;  R[NC + n + 3] = fmaf(p3, v, R[NC + n + 3]);
                p0 *= kq; p1 *= kq; p2 *= kq; p3 *= kq;
            }
        }
    }

    // ---- Transpose-exchange warp reduce: all 32 values in 5 shuffle rounds.
    // After the loop, lane l holds the warp-sum of value index l in R[l].
#pragma unroll
    for (int s = 16; s > 0; s >>= 1) {
        const bool up = (lane & s) != 0;
#pragma unroll
        for (int i0 = 0; i0 < 32; i0++) {
            if ((i0 & s) == 0) {
                const int i1 = i0 | s;
                const float send = up ? R[i0] : R[i1];
                const float recv = __shfl_xor_sync(0xffffffffu, send, s);
                if (up) R[i1] += recv; else R[i0] += recv;
            }
        }
    }
    float mine = R[0];
#pragma unroll
    for (int i = 1; i < 32; i++) mine = (lane == i) ? R[i] : mine;
    wR[wid][lane] = mine;

#pragma unroll
    for (int o = 16; o > 0; o >>= 1)
        kam = fmaxf(kam, __shfl_xor_sync(0xffffffffu, kam, o));
    if (lane == 0) wkam[wid] = kam;
    __syncthreads();

    // ---- Cross-warp finalize: c_n = (Σ_w wR[w][n]) / n!
    if (tid < 32) {
        float s = 0.f;
#pragma unroll
        for (int w = 0; w < NWARPS; w++) s += wR[w][tid];
        if (tid < NC) cS[tid] = s * c_invfact[tid];
        else          cM[tid - NC] = s * c_invfact[tid - NC];
    } else if (tid == 32) {
        float a = 0.f;
#pragma unroll
        for (int w = 0; w < NWARPS; w++) a = fmaxf(a, wkam[w]);
        s_kam = a;
    }
    __syncthreads();

    if (!act) return;

    const float kamf = s_kam;
    const float w0h  = W0[h];
    float* __restrict__ ob = out + b * G_DIM;

    // ---- Row eval straight from retained registers (no reloads).
    const float u0 = xv.x * qw.x, u1 = xv.y * qw.y, u2 = xv.z * qw.z, u3 = xv.w * qw.w;
    const float umax = fmaxf(fmaxf(fabsf(u0), fabsf(u1)), fmaxf(fabsf(u2), fabsf(u3)));

    float o0, o1, o2, o3;
    if (umax * kamf <= GUARD) {
        float d0 = cS[NC - 1], d1 = d0, d2 = d0, d3 = d0;
        float m0 = cM[NC - 1], m1 = m0, m2 = m0, m3 = m0;
#pragma unroll
        for (int n = NC - 2; n >= 0; n--) {
            const float cs = cS[n], cm = cM[n];
            d0 = fmaf(d0, u0, cs);  m0 = fmaf(m0, u0, cm);
            d1 = fmaf(d1, u1, cs);  m1 = fmaf(m1, u1, cm);
            d2 = fmaf(d2, u2, cs);  m2 = fmaf(m2, u2, cm);
            d3 = fmaf(d3, u3, cs);  m3 = fmaf(m3, u3, cm);
        }
        // diagonal masked post-softmax: subtract exp(u*k_i)*v_i from numerator
        const float e0 = __expf(u0 * k0);
        const float e1 = __expf(u1 * k1);
        const float e2 = __expf(u2 * k2);
        const float e3 = __expf(u3 * k3);
        o0 = (m0 - e0 * v0) * __frcp_rn(d0);
        o1 = (m1 - e1 * v1) * __frcp_rn(d1);
        o2 = (m2 - e2 * v2) * __frcp_rn(d2);
        o3 = (m3 - e3 * v3) * __frcp_rn(d3);
    } else {
        const float* xb = x  + b * G_DIM;
        const float* wk = WK + h * G_DIM;
        const float* wv = WV + h * G_DIM;
        o0 = exact_row(u0, xb, wk, wv, kamf, k0, v0);
        o1 = exact_row(u1, xb, wk, wv, kamf, k1, v1);
        o2 = exact_row(u2, xb, wk, wv, kamf, k2, v2);
        o3 = exact_row(u3, xb, wk, wv, kamf, k3, v3);
    }
    const int i = 4 * tid;
    atomicAdd(ob + i + 0, w0h * o0);
    atomicAdd(ob + i + 1, w0h * o1);
    atomicAdd(ob + i + 2, w0h * o2);
    atomicAdd(ob + i + 3, w0h * o3);
}

extern "C" void kernel_launch(void* const* d_in, const int* in_sizes, int n_in,
                              void* d_out, int out_size) {
    const float* x  = (const float*)d_in[0];
    const float* WQ = (const float*)d_in[1];
    const float* WK = (const float*)d_in[2];
    const float* WV = (const float*)d_in[3];
    const float* W0 = (const float*)d_in[4];
    float* out = (float*)d_out;

    // Zero the accumulator (graph-capturable memset node; no allocation).
    cudaMemsetAsync(out, 0, (size_t)out_size * sizeof(float), 0);

    dim3 grid(B_DIM, H_DIM);
    attn_head_red_kernel<<<grid, NTHREADS>>>(x, WQ, WK, WV, W0, out);
}